// round 2
// baseline (speedup 1.0000x reference)
#include <cuda_runtime.h>

#define ND 128
#define ED 32
#define HD 256
#define IN1 288          // 2*ND + ED
#define TE 64            // edges / nodes per block
#define NT 256           // threads per block
#define BK 16            // K-slab staged in smem

// Scratch: aggregation buffer (scatter-add target). 50000*128 fp32 = 25.6 MB.
__device__ float g_aggr[(size_t)50000 * ND];

__global__ void zero_kernel(int n) {
    int i = blockIdx.x * blockDim.x + threadIdx.x;
    int stride = gridDim.x * blockDim.x;
    for (; i < n; i += stride) g_aggr[i] = 0.0f;
}

// Block GEMM: A_s [TE][lda] (smem) x W [K][NCOL] (gmem, staged via w_s) + bias.
// Thread (tx,ty) computes rows ty*8..ty*8+7, cols {tx + j*32 : j<JT}.
// a-reads are warp-broadcast; b-reads and tile loads are conflict-free.
template<int K, int NCOL, int JT>
__device__ __forceinline__ void gemm_tile(
    const float* __restrict__ A_s, int lda,
    const float* __restrict__ W, const float* __restrict__ bias,
    float* w_s, float (&acc)[8][JT], int tid)
{
    const int tx = tid & 31, ty = tid >> 5;
    #pragma unroll
    for (int j = 0; j < JT; j++) {
        float bj = bias[tx + j * 32];
        #pragma unroll
        for (int i = 0; i < 8; i++) acc[i][j] = bj;
    }
    #pragma unroll 1
    for (int k0 = 0; k0 < K; k0 += BK) {
        __syncthreads();   // protect w_s (and A_s on first pass)
        #pragma unroll
        for (int l = 0; l < (BK * NCOL) / NT; l++) {
            int idx = l * NT + tid;
            w_s[idx] = W[(k0 + idx / NCOL) * NCOL + (idx % NCOL)];
        }
        __syncthreads();
        #pragma unroll
        for (int kk = 0; kk < BK; kk++) {
            float a[8], b[JT];
            #pragma unroll
            for (int i = 0; i < 8; i++) a[i] = A_s[(ty * 8 + i) * lda + k0 + kk];
            #pragma unroll
            for (int j = 0; j < JT; j++) b[j] = w_s[kk * NCOL + tx + j * 32];
            #pragma unroll
            for (int i = 0; i < 8; i++)
                #pragma unroll
                for (int j = 0; j < JT; j++)
                    acc[i][j] = fmaf(a[i], b[j], acc[i][j]);
        }
    }
    __syncthreads();
}

// Edge pipeline: gather [x[row] | x[col] | edge_attr] -> MLP(288->256->256->128)
// -> scatter-add into g_aggr[col].
__global__ __launch_bounds__(NT) void edge_kernel(
    const float* __restrict__ x, const int* __restrict__ ei,
    const float* __restrict__ ea,
    const float* __restrict__ W1, const float* __restrict__ b1,
    const float* __restrict__ W2, const float* __restrict__ b2,
    const float* __restrict__ W3, const float* __restrict__ b3,
    int E)
{
    extern __shared__ float smem[];
    float* in_s = smem;                    // [TE][IN1]  (reused for h2 [TE][<=IN1])
    float* h_s  = in_s + TE * IN1;         // [TE][HD]
    float* w_s  = h_s + TE * HD;           // [BK][HD]
    int*   idx_s = (int*)(w_s + BK * HD);  // row[TE], col[TE]
    int* row_s = idx_s;
    int* col_s = idx_s + TE;

    const int tid = threadIdx.x;
    const int tx = tid & 31, ty = tid >> 5;
    const int e0 = blockIdx.x * TE;

    // Load edge endpoint indices (int32, layout [2][E])
    if (tid < 2 * TE) {
        int k = tid & (TE - 1);
        int which = tid >> 6;                 // 0: row, 1: col
        int e = e0 + k;
        int v = 0;
        if (e < E) v = ei[(size_t)which * E + e];
        idx_s[tid] = v;
    }
    __syncthreads();

    // Gather features as float4: per edge 72 float4 = 32 (x[row]) + 32 (x[col]) + 8 (ea)
    for (int t = tid; t < TE * 72; t += NT) {
        int e = t / 72, j = t % 72;
        float4 v;
        int dstoff;
        if (e0 + e < E) {
            if (j < 32)      { v = ((const float4*)(x + (size_t)row_s[e] * ND))[j];        dstoff = j * 4; }
            else if (j < 64) { v = ((const float4*)(x + (size_t)col_s[e] * ND))[j - 32];   dstoff = 128 + (j - 32) * 4; }
            else             { v = ((const float4*)(ea + (size_t)(e0 + e) * ED))[j - 64];  dstoff = 256 + (j - 64) * 4; }
        } else {
            v = make_float4(0.f, 0.f, 0.f, 0.f);
            dstoff = (j < 32) ? j * 4 : (j < 64) ? 128 + (j - 32) * 4 : 256 + (j - 64) * 4;
        }
        float* d = in_s + e * IN1 + dstoff;
        d[0] = v.x; d[1] = v.y; d[2] = v.z; d[3] = v.w;
    }

    // GEMM1: [64,288] x [288,256] -> relu -> h_s
    float acc[8][8];
    gemm_tile<IN1, HD, 8>(in_s, IN1, W1, b1, w_s, acc, tid);
    #pragma unroll
    for (int i = 0; i < 8; i++)
        #pragma unroll
        for (int j = 0; j < 8; j++)
            h_s[(ty * 8 + i) * HD + tx + j * 32] = fmaxf(acc[i][j], 0.0f);

    // GEMM2: [64,256] x [256,256] -> relu -> h2 (stored back into in_s region)
    gemm_tile<HD, HD, 8>(h_s, HD, W2, b2, w_s, acc, tid);
    #pragma unroll
    for (int i = 0; i < 8; i++)
        #pragma unroll
        for (int j = 0; j < 8; j++)
            in_s[(ty * 8 + i) * IN1 + tx + j * 32] = fmaxf(acc[i][j], 0.0f);

    // GEMM3: [64,256] x [256,128] -> edge_out, scatter-add to g_aggr[col]
    float acc3[8][4];
    gemm_tile<HD, ND, 4>(in_s, IN1, W3, b3, w_s, acc3, tid);

    #pragma unroll
    for (int i = 0; i < 8; i++) {
        int k = ty * 8 + i;
        if (e0 + k < E) {
            float* dst = g_aggr + (size_t)col_s[k] * ND + tx;
            #pragma unroll
            for (int j = 0; j < 4; j++)
                atomicAdd(dst + j * 32, acc3[i][j]);   // ptxas -> RED.E.ADD (coalesced per warp)
        }
    }
}

// Node pipeline: [x | aggr] -> MLP(256->256->128) -> residual -> LayerNorm -> out
__global__ __launch_bounds__(NT) void node_kernel(
    const float* __restrict__ x,
    const float* __restrict__ Wn1, const float* __restrict__ bn1,
    const float* __restrict__ Wn2, const float* __restrict__ bn2,
    const float* __restrict__ gamma, const float* __restrict__ beta,
    float* __restrict__ out, int Nn)
{
    extern __shared__ float smem[];
    float* in_s = smem;             // [TE][HD] : cols 0..127 = x, 128..255 = aggr
    float* h_s  = in_s + TE * HD;   // [TE][HD]
    float* w_s  = h_s + TE * HD;    // [BK][HD]

    const int tid = threadIdx.x;
    const int tx = tid & 31, ty = tid >> 5;
    const int n0 = blockIdx.x * TE;

    for (int t = tid; t < TE * 64; t += NT) {
        int r = t >> 6, j = t & 63;
        int n = n0 + r; if (n >= Nn) n = Nn - 1;   // clamp (stores are guarded)
        float4 v = (j < 32) ? ((const float4*)(x + (size_t)n * ND))[j]
                            : ((const float4*)(g_aggr + (size_t)n * ND))[j - 32];
        float* d = in_s + r * HD + j * 4;
        d[0] = v.x; d[1] = v.y; d[2] = v.z; d[3] = v.w;
    }

    float acc[8][8];
    gemm_tile<HD, HD, 8>(in_s, HD, Wn1, bn1, w_s, acc, tid);
    #pragma unroll
    for (int i = 0; i < 8; i++)
        #pragma unroll
        for (int j = 0; j < 8; j++)
            h_s[(ty * 8 + i) * HD + tx + j * 32] = fmaxf(acc[i][j], 0.0f);

    float acc2[8][4];
    gemm_tile<HD, ND, 4>(h_s, HD, Wn2, bn2, w_s, acc2, tid);

    // residual: y = x + node_out, stored into in_s cols 0..127 (each element single-owner)
    #pragma unroll
    for (int i = 0; i < 8; i++) {
        int r = ty * 8 + i;
        #pragma unroll
        for (int j = 0; j < 4; j++) {
            int c = tx + j * 32;
            in_s[r * HD + c] += acc2[i][j];
        }
    }
    __syncthreads();

    // LayerNorm: warp ty handles rows ty*8 .. ty*8+7, one full-warp reduce per row
    #pragma unroll 1
    for (int rr = 0; rr < 8; rr++) {
        int r = ty * 8 + rr;
        float4 v = *(const float4*)(in_s + r * HD + tx * 4);
        float s  = v.x + v.y + v.z + v.w;
        float sq = v.x * v.x + v.y * v.y + v.z * v.z + v.w * v.w;
        #pragma unroll
        for (int o = 16; o > 0; o >>= 1) {
            s  += __shfl_xor_sync(0xffffffffu, s, o);
            sq += __shfl_xor_sync(0xffffffffu, sq, o);
        }
        float mean = s * (1.0f / ND);
        float var  = sq * (1.0f / ND) - mean * mean;
        float rstd = rsqrtf(var + 1e-5f);
        int n = n0 + r;
        if (n < Nn) {
            float4 g  = ((const float4*)gamma)[tx];
            float4 bb = ((const float4*)beta)[tx];
            float4 o4;
            o4.x = (v.x - mean) * rstd * g.x + bb.x;
            o4.y = (v.y - mean) * rstd * g.y + bb.y;
            o4.z = (v.z - mean) * rstd * g.z + bb.z;
            o4.w = (v.w - mean) * rstd * g.w + bb.w;
            ((float4*)(out + (size_t)n * ND))[tx] = o4;
        }
    }
}

extern "C" void kernel_launch(void* const* d_in, const int* in_sizes, int n_in,
                              void* d_out, int out_size) {
    const float* x   = (const float*)d_in[0];
    const int*   ei  = (const int*)d_in[1];
    const float* ea  = (const float*)d_in[2];
    const float* W1  = (const float*)d_in[3];
    const float* b1  = (const float*)d_in[4];
    const float* W2  = (const float*)d_in[5];
    const float* b2  = (const float*)d_in[6];
    const float* W3  = (const float*)d_in[7];
    const float* b3  = (const float*)d_in[8];
    const float* Wn1 = (const float*)d_in[9];
    const float* bn1 = (const float*)d_in[10];
    const float* Wn2 = (const float*)d_in[11];
    const float* bn2 = (const float*)d_in[12];
    const float* gm  = (const float*)d_in[13];
    const float* bt  = (const float*)d_in[14];
    float* out = (float*)d_out;

    const int N = in_sizes[0] / ND;
    const int E = in_sizes[1] / 2;

    const int EDGE_SMEM = (TE * IN1 + TE * HD + BK * HD) * 4 + 2 * TE * 4;
    const int NODE_SMEM = (TE * HD * 2 + BK * HD) * 4;
    cudaFuncSetAttribute(edge_kernel, cudaFuncAttributeMaxDynamicSharedMemorySize, EDGE_SMEM);
    cudaFuncSetAttribute(node_kernel, cudaFuncAttributeMaxDynamicSharedMemorySize, NODE_SMEM);

    int zero_blocks = (N * ND + 255) / 256;
    if (zero_blocks > 4096) zero_blocks = 4096;
    zero_kernel<<<zero_blocks, 256>>>(N * ND);

    edge_kernel<<<(E + TE - 1) / TE, NT, EDGE_SMEM>>>(
        x, ei, ea, W1, b1, W2, b2, W3, b3, E);

    node_kernel<<<(N + TE - 1) / TE, NT, NODE_SMEM>>>(
        x, Wn1, bn1, Wn2, bn2, gm, bt, out, N);
}

// round 3
// speedup vs baseline: 2.5630x; 2.5630x over previous
#include <cuda_runtime.h>
#include <cstdint>

#define ND 128
#define ED 32
#define HD 256
#define IN1 288          // 2*ND + ED
#define TE 64            // edges per block (M tile)
#define NT 256           // threads per block (8 warps: 4 in M x 2 in N)
#define LDA 292          // padded A row stride (floats): 292*4 % 128 == 16 -> conflict-free LDSM

// Scratch: aggregation buffer (scatter-add target). 50000*128 fp32 = 25.6 MB.
__device__ float g_aggr[(size_t)50000 * ND];

__global__ void zero_kernel(int n) {
    int i = blockIdx.x * blockDim.x + threadIdx.x;
    int stride = gridDim.x * blockDim.x;
    for (; i < n; i += stride) g_aggr[i] = 0.0f;
}

__device__ __forceinline__ float to_tf32(float x) {
    uint32_t r; asm("cvt.rna.tf32.f32 %0, %1;" : "=r"(r) : "f"(x));
    return __uint_as_float(r);
}

__device__ __forceinline__ void mma_tf32(float (&c)[4], uint32_t a0, uint32_t a1,
                                         uint32_t a2, uint32_t a3, uint32_t b0, uint32_t b1) {
    asm volatile("mma.sync.aligned.m16n8k8.row.col.f32.tf32.tf32.f32 "
        "{%0,%1,%2,%3}, {%4,%5,%6,%7}, {%8,%9}, {%0,%1,%2,%3};"
        : "+f"(c[0]), "+f"(c[1]), "+f"(c[2]), "+f"(c[3])
        : "r"(a0), "r"(a1), "r"(a2), "r"(a3), "r"(b0), "r"(b1));
}

__device__ __forceinline__ void ldsm4(uint32_t &a0, uint32_t &a1, uint32_t &a2, uint32_t &a3,
                                      const float* p) {
    uint32_t addr = (uint32_t)__cvta_generic_to_shared(p);
    asm volatile("ldmatrix.sync.aligned.m8n8.x4.shared.b16 {%0,%1,%2,%3}, [%4];"
        : "=r"(a0), "=r"(a1), "=r"(a2), "=r"(a3) : "r"(addr));
}

// Warp-tiled tf32 GEMM: A_s [TE][LDA] (smem, tf32-rounded) x W [K][N] (gmem, row-major).
// Warp (wm, wn) computes rows wm*16..+16, cols wn*(N/2)..+(N/2). acc zeroed here.
// W is staged per 32-row K-slab into w_s in MMA B-fragment order:
//   w_s[((kk*NT8 + nt)*32 + lane)] = float2( W[k0+kk*8+lane%4][nt*8+lane/4],
//                                            W[k0+kk*8+lane%4+4][nt*8+lane/4] )
template<int K, int N>
__device__ __forceinline__ void do_gemm(const float* A_s, const float* __restrict__ W,
                                        float2* w_s, float (&acc)[16][4], int tid) {
    const int l = tid & 31, wid = tid >> 5;
    const int wm = wid & 3, wn = wid >> 2;
    constexpr int NT8 = N / 8;    // total n-subtiles
    constexpr int NTW = N / 16;   // per-warp n-subtiles

    #pragma unroll
    for (int nt = 0; nt < NTW; nt++)
        #pragma unroll
        for (int i = 0; i < 4; i++) acc[nt][i] = 0.0f;

    // per-lane ldmatrix source row/col-base
    const int a_row = wm * 16 + ((l >> 3) & 1) * 8 + (l & 7);
    const int a_col4 = (l >> 4) * 4;

    #pragma unroll 1
    for (int k0 = 0; k0 < K; k0 += 32) {
        __syncthreads();
        #pragma unroll
        for (int d = tid; d < 4 * NT8 * 32; d += NT) {
            int kk = d / (NT8 * 32);
            int nt = (d >> 5) % NT8;
            int ll = d & 31;
            int k = k0 + kk * 8 + (ll & 3);
            int n = nt * 8 + (ll >> 2);
            float2 v;
            v.x = to_tf32(W[(size_t)k * N + n]);
            v.y = to_tf32(W[(size_t)(k + 4) * N + n]);
            w_s[d] = v;
        }
        __syncthreads();
        #pragma unroll
        for (int kk = 0; kk < 4; kk++) {
            uint32_t a0, a1, a2, a3;
            ldsm4(a0, a1, a2, a3, A_s + a_row * LDA + k0 + kk * 8 + a_col4);
            #pragma unroll
            for (int nt = 0; nt < NTW; nt++) {
                float2 b = w_s[(size_t)(kk * NT8 + wn * NTW + nt) * 32 + l];
                mma_tf32(acc[nt], a0, a1, a2, a3,
                         __float_as_uint(b.x), __float_as_uint(b.y));
            }
        }
    }
    __syncthreads();
}

// Epilogue: acc + bias (+ReLU), store tf32-rounded back to A_s.
template<int NTW, bool RELU>
__device__ __forceinline__ void epi_store(float (&acc)[16][4], const float* __restrict__ bias,
                                          float* A_s, int tid) {
    const int l = tid & 31, wid = tid >> 5;
    const int wm = wid & 3, wn = wid >> 2;
    const int r0 = wm * 16 + (l >> 2);
    #pragma unroll
    for (int nt = 0; nt < NTW; nt++) {
        int c0 = (wn * NTW + nt) * 8 + (l & 3) * 2;
        float bb0 = bias[c0], bb1 = bias[c0 + 1];
        float v00 = acc[nt][0] + bb0, v01 = acc[nt][1] + bb1;
        float v10 = acc[nt][2] + bb0, v11 = acc[nt][3] + bb1;
        if (RELU) {
            v00 = fmaxf(v00, 0.0f); v01 = fmaxf(v01, 0.0f);
            v10 = fmaxf(v10, 0.0f); v11 = fmaxf(v11, 0.0f);
        }
        A_s[r0 * LDA + c0]           = to_tf32(v00);
        A_s[r0 * LDA + c0 + 1]       = to_tf32(v01);
        A_s[(r0 + 8) * LDA + c0]     = to_tf32(v10);
        A_s[(r0 + 8) * LDA + c0 + 1] = to_tf32(v11);
    }
}

// Edge pipeline: gather [x[row] | x[col] | edge_attr] -> tf32 MMA MLP(288->256->256->128)
// -> scatter-add into g_aggr[col].
__global__ __launch_bounds__(NT, 2) void edge_kernel(
    const float* __restrict__ x, const int* __restrict__ ei,
    const float* __restrict__ ea,
    const float* __restrict__ W1, const float* __restrict__ b1,
    const float* __restrict__ W2, const float* __restrict__ b2,
    const float* __restrict__ W3, const float* __restrict__ b3,
    int E)
{
    extern __shared__ float smem[];
    float*  A_s  = smem;                          // [TE][LDA]
    float2* w_s  = (float2*)(A_s + TE * LDA);     // 4*32*32 = 4096 float2 (max)
    int*    idx_s = (int*)(w_s + 4096);           // row[TE], col[TE]
    int* row_s = idx_s;
    int* col_s = idx_s + TE;

    const int tid = threadIdx.x;
    const int l = tid & 31, wid = tid >> 5;
    const int wm = wid & 3, wn = wid >> 2;
    const int e0 = blockIdx.x * TE;

    // Load edge endpoint indices (int32, layout [2][E])
    if (tid < 2 * TE) {
        int k = tid & (TE - 1);
        int which = tid >> 6;                 // 0: row, 1: col
        int e = e0 + k;
        int v = 0;
        if (e < E) v = ei[(size_t)which * E + e];
        idx_s[tid] = v;
    }
    __syncthreads();

    // Gather features (tf32-rounded): per edge 72 float4 = x[row] | x[col] | ea
    for (int t = tid; t < TE * 72; t += NT) {
        int e = t / 72, j = t % 72;
        float4 v;
        int dstoff;
        if (e0 + e < E) {
            if (j < 32)      { v = ((const float4*)(x + (size_t)row_s[e] * ND))[j];        dstoff = j * 4; }
            else if (j < 64) { v = ((const float4*)(x + (size_t)col_s[e] * ND))[j - 32];   dstoff = 128 + (j - 32) * 4; }
            else             { v = ((const float4*)(ea + (size_t)(e0 + e) * ED))[j - 64];  dstoff = 256 + (j - 64) * 4; }
        } else {
            v = make_float4(0.f, 0.f, 0.f, 0.f);
            dstoff = (j < 32) ? j * 4 : (j < 64) ? 128 + (j - 32) * 4 : 256 + (j - 64) * 4;
        }
        float* d = A_s + e * LDA + dstoff;
        d[0] = to_tf32(v.x); d[1] = to_tf32(v.y); d[2] = to_tf32(v.z); d[3] = to_tf32(v.w);
    }
    // (first __syncthreads inside do_gemm protects A_s)

    float acc[16][4];

    // GEMM1: [64,288] x [288,256] -> relu -> A_s
    do_gemm<IN1, HD>(A_s, W1, w_s, acc, tid);
    epi_store<16, true>(acc, b1, A_s, tid);

    // GEMM2: [64,256] x [256,256] -> relu -> A_s
    do_gemm<HD, HD>(A_s, W2, w_s, acc, tid);
    epi_store<16, true>(acc, b2, A_s, tid);

    // GEMM3: [64,256] x [256,128] -> +b3 -> scatter-add to g_aggr[col]
    do_gemm<HD, ND>(A_s, W3, w_s, acc, tid);
    {
        const int r0 = wm * 16 + (l >> 2);
        const int r1 = r0 + 8;
        const bool ok0 = (e0 + r0) < E, ok1 = (e0 + r1) < E;
        float* dst0 = g_aggr + (size_t)col_s[r0] * ND;
        float* dst1 = g_aggr + (size_t)col_s[r1] * ND;
        #pragma unroll
        for (int nt = 0; nt < 8; nt++) {
            int c0 = (wn * 8 + nt) * 8 + (l & 3) * 2;
            float bb0 = b3[c0], bb1 = b3[c0 + 1];
            if (ok0) {
                atomicAdd(dst0 + c0,     acc[nt][0] + bb0);
                atomicAdd(dst0 + c0 + 1, acc[nt][1] + bb1);
            }
            if (ok1) {
                atomicAdd(dst1 + c0,     acc[nt][2] + bb0);
                atomicAdd(dst1 + c0 + 1, acc[nt][3] + bb1);
            }
        }
    }
}

// ---------------- Node pipeline (SIMT fp32, unchanged) ----------------
#define BK 16

template<int K, int NCOL, int JT>
__device__ __forceinline__ void gemm_tile(
    const float* __restrict__ A_s, int lda,
    const float* __restrict__ W, const float* __restrict__ bias,
    float* w_s, float (&acc)[8][JT], int tid)
{
    const int tx = tid & 31, ty = tid >> 5;
    #pragma unroll
    for (int j = 0; j < JT; j++) {
        float bj = bias[tx + j * 32];
        #pragma unroll
        for (int i = 0; i < 8; i++) acc[i][j] = bj;
    }
    #pragma unroll 1
    for (int k0 = 0; k0 < K; k0 += BK) {
        __syncthreads();
        #pragma unroll
        for (int lld = 0; lld < (BK * NCOL) / NT; lld++) {
            int idx = lld * NT + tid;
            w_s[idx] = W[(k0 + idx / NCOL) * NCOL + (idx % NCOL)];
        }
        __syncthreads();
        #pragma unroll
        for (int kk = 0; kk < BK; kk++) {
            float a[8], b[JT];
            #pragma unroll
            for (int i = 0; i < 8; i++) a[i] = A_s[(ty * 8 + i) * lda + k0 + kk];
            #pragma unroll
            for (int j = 0; j < JT; j++) b[j] = w_s[kk * NCOL + tx + j * 32];
            #pragma unroll
            for (int i = 0; i < 8; i++)
                #pragma unroll
                for (int j = 0; j < JT; j++)
                    acc[i][j] = fmaf(a[i], b[j], acc[i][j]);
        }
    }
    __syncthreads();
}

__global__ __launch_bounds__(NT) void node_kernel(
    const float* __restrict__ x,
    const float* __restrict__ Wn1, const float* __restrict__ bn1,
    const float* __restrict__ Wn2, const float* __restrict__ bn2,
    const float* __restrict__ gamma, const float* __restrict__ beta,
    float* __restrict__ out, int Nn)
{
    extern __shared__ float smem[];
    float* in_s = smem;             // [TE][HD] : cols 0..127 = x, 128..255 = aggr
    float* h_s  = in_s + TE * HD;   // [TE][HD]
    float* w_s  = h_s + TE * HD;    // [BK][HD]

    const int tid = threadIdx.x;
    const int tx = tid & 31, ty = tid >> 5;
    const int n0 = blockIdx.x * TE;

    for (int t = tid; t < TE * 64; t += NT) {
        int r = t >> 6, j = t & 63;
        int n = n0 + r; if (n >= Nn) n = Nn - 1;   // clamp (stores are guarded)
        float4 v = (j < 32) ? ((const float4*)(x + (size_t)n * ND))[j]
                            : ((const float4*)(g_aggr + (size_t)n * ND))[j - 32];
        float* d = in_s + r * HD + j * 4;
        d[0] = v.x; d[1] = v.y; d[2] = v.z; d[3] = v.w;
    }

    float acc[8][8];
    gemm_tile<HD, HD, 8>(in_s, HD, Wn1, bn1, w_s, acc, tid);
    #pragma unroll
    for (int i = 0; i < 8; i++)
        #pragma unroll
        for (int j = 0; j < 8; j++)
            h_s[(ty * 8 + i) * HD + tx + j * 32] = fmaxf(acc[i][j], 0.0f);

    float acc2[8][4];
    gemm_tile<HD, ND, 4>(h_s, HD, Wn2, bn2, w_s, acc2, tid);

    #pragma unroll
    for (int i = 0; i < 8; i++) {
        int r = ty * 8 + i;
        #pragma unroll
        for (int j = 0; j < 4; j++) {
            int c = tx + j * 32;
            in_s[r * HD + c] += acc2[i][j];
        }
    }
    __syncthreads();

    #pragma unroll 1
    for (int rr = 0; rr < 8; rr++) {
        int r = ty * 8 + rr;
        float4 v = *(const float4*)(in_s + r * HD + tx * 4);
        float s  = v.x + v.y + v.z + v.w;
        float sq = v.x * v.x + v.y * v.y + v.z * v.z + v.w * v.w;
        #pragma unroll
        for (int o = 16; o > 0; o >>= 1) {
            s  += __shfl_xor_sync(0xffffffffu, s, o);
            sq += __shfl_xor_sync(0xffffffffu, sq, o);
        }
        float mean = s * (1.0f / ND);
        float var  = sq * (1.0f / ND) - mean * mean;
        float rstd = rsqrtf(var + 1e-5f);
        int n = n0 + r;
        if (n < Nn) {
            float4 g  = ((const float4*)gamma)[tx];
            float4 bb = ((const float4*)beta)[tx];
            float4 o4;
            o4.x = (v.x - mean) * rstd * g.x + bb.x;
            o4.y = (v.y - mean) * rstd * g.y + bb.y;
            o4.z = (v.z - mean) * rstd * g.z + bb.z;
            o4.w = (v.w - mean) * rstd * g.w + bb.w;
            ((float4*)(out + (size_t)n * ND))[tx] = o4;
        }
    }
}

extern "C" void kernel_launch(void* const* d_in, const int* in_sizes, int n_in,
                              void* d_out, int out_size) {
    const float* x   = (const float*)d_in[0];
    const int*   ei  = (const int*)d_in[1];
    const float* ea  = (const float*)d_in[2];
    const float* W1  = (const float*)d_in[3];
    const float* b1  = (const float*)d_in[4];
    const float* W2  = (const float*)d_in[5];
    const float* b2  = (const float*)d_in[6];
    const float* W3  = (const float*)d_in[7];
    const float* b3  = (const float*)d_in[8];
    const float* Wn1 = (const float*)d_in[9];
    const float* bn1 = (const float*)d_in[10];
    const float* Wn2 = (const float*)d_in[11];
    const float* bn2 = (const float*)d_in[12];
    const float* gm  = (const float*)d_in[13];
    const float* bt  = (const float*)d_in[14];
    float* out = (float*)d_out;

    const int N = in_sizes[0] / ND;
    const int E = in_sizes[1] / 2;

    const int EDGE_SMEM = TE * LDA * 4 + 4096 * 8 + 2 * TE * 4;     // ~108 KB
    const int NODE_SMEM = (TE * HD * 2 + BK * HD) * 4;
    cudaFuncSetAttribute(edge_kernel, cudaFuncAttributeMaxDynamicSharedMemorySize, EDGE_SMEM);
    cudaFuncSetAttribute(node_kernel, cudaFuncAttributeMaxDynamicSharedMemorySize, NODE_SMEM);

    int zero_blocks = (N * ND + 255) / 256;
    if (zero_blocks > 4096) zero_blocks = 4096;
    zero_kernel<<<zero_blocks, 256>>>(N * ND);

    edge_kernel<<<(E + TE - 1) / TE, NT, EDGE_SMEM>>>(
        x, ei, ea, W1, b1, W2, b2, W3, b3, E);

    node_kernel<<<(N + TE - 1) / TE, NT, NODE_SMEM>>>(
        x, Wn1, bn1, Wn2, bn2, gm, bt, out, N);
}

// round 7
// speedup vs baseline: 3.4556x; 1.3483x over previous
#include <cuda_runtime.h>
#include <cstdint>

#define ND 128
#define ED 32
#define HD 256
#define IN1 288          // 2*ND + ED
#define TE 128           // edges per block (M tile)
#define NTE 512          // edge kernel threads (16 warps: 8 in M x 2 in N)
#define LDA 292          // padded A row stride (floats): 292*4 % 128 == 16 -> conflict-free LDSM
#define WBUF 2048        // double-buffer stride in float4 (max slab = 32KB)

// Scratch: aggregation buffer (scatter-add target). 50000*128 fp32 = 25.6 MB.
__device__ float g_aggr[(size_t)50000 * ND];
// Pre-permuted tf32 weight fragments (B-fragment order), written by perm_kernel.
// Fragment storage = K*N/2 float2 = K*N/4 float4.
__device__ float4 g_W1f[IN1 * HD / 4];   // 18432 float4
__device__ float4 g_W2f[HD * HD / 4];    // 16384 float4
__device__ float4 g_W3f[HD * ND / 4];    // 8192 float4

__global__ void zero_kernel(int n) {
    int i = blockIdx.x * blockDim.x + threadIdx.x;
    int stride = gridDim.x * blockDim.x;
    for (; i < n; i += stride) g_aggr[i] = 0.0f;
}

__device__ __forceinline__ float to_tf32(float x) {
    uint32_t r; asm("cvt.rna.tf32.f32 %0, %1;" : "=r"(r) : "f"(x));
    return __uint_as_float(r);
}

// Permute W [K][N] (row-major) into MMA B-fragment slab order.
// Destination selected in DEVICE code: a __device__ array referenced from host
// code gives the host shadow address (and HMM happily writes host memory!),
// so the device symbol must be resolved here.
// linear fragment index i: l=i&31; nt=(i>>5)%(N/8); q=(i>>5)/(N/8); kk=q&3; s=q>>2;
// value = float2( tf32(W[s*32+kk*8+(l&3)][nt*8+(l>>2)]),
//                 tf32(W[s*32+kk*8+(l&3)+4][nt*8+(l>>2)]) )
__global__ void perm_kernel(const float* __restrict__ W, int K, int N, int which) {
    float2* Wf = (which == 0) ? (float2*)g_W1f
               : (which == 1) ? (float2*)g_W2f
                              : (float2*)g_W3f;
    int i = blockIdx.x * blockDim.x + threadIdx.x;
    int total = K * N / 2;
    if (i >= total) return;
    int l = i & 31;
    int t = i >> 5;
    int nt = t % (N >> 3);
    int q = t / (N >> 3);
    int kk = q & 3, s = q >> 2;
    int k = s * 32 + kk * 8 + (l & 3);
    int n = nt * 8 + (l >> 2);
    float2 v;
    v.x = to_tf32(W[(size_t)k * N + n]);
    v.y = to_tf32(W[(size_t)(k + 4) * N + n]);
    Wf[i] = v;
}

__device__ __forceinline__ void mma_tf32(float (&c)[4], uint32_t a0, uint32_t a1,
                                         uint32_t a2, uint32_t a3, uint32_t b0, uint32_t b1) {
    asm volatile("mma.sync.aligned.m16n8k8.row.col.f32.tf32.tf32.f32 "
        "{%0,%1,%2,%3}, {%4,%5,%6,%7}, {%8,%9}, {%0,%1,%2,%3};"
        : "+f"(c[0]), "+f"(c[1]), "+f"(c[2]), "+f"(c[3])
        : "r"(a0), "r"(a1), "r"(a2), "r"(a3), "r"(b0), "r"(b1));
}

__device__ __forceinline__ void ldsm4(uint32_t &a0, uint32_t &a1, uint32_t &a2, uint32_t &a3,
                                      const float* p) {
    uint32_t addr = (uint32_t)__cvta_generic_to_shared(p);
    asm volatile("ldmatrix.sync.aligned.m8n8.x4.shared.b16 {%0,%1,%2,%3}, [%4];"
        : "=r"(a0), "=r"(a1), "=r"(a2), "=r"(a3) : "r"(addr));
}

__device__ __forceinline__ void cp_async16(void* smem_dst, const void* gsrc) {
    uint32_t d = (uint32_t)__cvta_generic_to_shared(smem_dst);
    asm volatile("cp.async.cg.shared.global [%0], [%1], 16;" :: "r"(d), "l"(gsrc));
}
__device__ __forceinline__ void cp_commit() { asm volatile("cp.async.commit_group;"); }
__device__ __forceinline__ void cp_wait0()  { asm volatile("cp.async.wait_group 0;"); }

// Warp-tiled tf32 GEMM: A_s [TE][LDA] (smem, tf32-rounded) x pre-permuted frags Wf4.
// 16 warps: wm = wid%8 (M), wn = wid/8 (N half). Double-buffered cp.async staging.
template<int K, int N>
__device__ __forceinline__ void do_gemm_frag(const float* A_s, const float4* __restrict__ Wf4,
                                             float4* w_s4, float (&acc)[16][4], int tid) {
    const int l = tid & 31, wid = tid >> 5;
    const int wm = wid & 7, wn = wid >> 3;
    constexpr int NT8 = N / 8;          // n-subtiles total
    constexpr int NTW = N / 16;         // n-subtiles per warp
    constexpr int SLAB4 = NT8 * 64;     // float4 per 32-K slab
    constexpr int S = K / 32;           // slab count

    #pragma unroll
    for (int nt = 0; nt < NTW; nt++)
        #pragma unroll
        for (int i = 0; i < 4; i++) acc[nt][i] = 0.0f;

    const int a_row = wm * 16 + ((l >> 3) & 1) * 8 + (l & 7);
    const int a_col4 = (l >> 4) * 4;

    // prologue: stage slab 0
    #pragma unroll
    for (int t = tid; t < SLAB4; t += NTE) cp_async16(w_s4 + t, Wf4 + t);
    cp_commit();

    #pragma unroll 1
    for (int s = 0; s < S; s++) {
        cp_wait0();
        __syncthreads();          // slab s ready; all warps past compute of s-1
        if (s + 1 < S) {
            float4* dst = w_s4 + ((s + 1) & 1) * WBUF;
            const float4* src = Wf4 + (size_t)(s + 1) * SLAB4;
            #pragma unroll
            for (int t = tid; t < SLAB4; t += NTE) cp_async16(dst + t, src + t);
            cp_commit();
        }
        const float2* wb = (const float2*)(w_s4 + (s & 1) * WBUF);
        const int k0 = s * 32;
        #pragma unroll
        for (int kk = 0; kk < 4; kk++) {
            uint32_t a0, a1, a2, a3;
            ldsm4(a0, a1, a2, a3, A_s + a_row * LDA + k0 + kk * 8 + a_col4);
            #pragma unroll
            for (int nt = 0; nt < NTW; nt++) {
                float2 b = wb[(size_t)(kk * NT8 + wn * NTW + nt) * 32 + l];
                mma_tf32(acc[nt], a0, a1, a2, a3,
                         __float_as_uint(b.x), __float_as_uint(b.y));
            }
        }
    }
    __syncthreads();   // protect A_s rewrite by epilogue
}

// Epilogue: acc + bias (+ReLU), store tf32-rounded back to A_s.
template<int NTW, bool RELU>
__device__ __forceinline__ void epi_store(float (&acc)[16][4], const float* __restrict__ bias,
                                          float* A_s, int tid) {
    const int l = tid & 31, wid = tid >> 5;
    const int wm = wid & 7, wn = wid >> 3;
    const int r0 = wm * 16 + (l >> 2);
    #pragma unroll
    for (int nt = 0; nt < NTW; nt++) {
        int c0 = (wn * NTW + nt) * 8 + (l & 3) * 2;
        float bb0 = bias[c0], bb1 = bias[c0 + 1];
        float v00 = acc[nt][0] + bb0, v01 = acc[nt][1] + bb1;
        float v10 = acc[nt][2] + bb0, v11 = acc[nt][3] + bb1;
        if (RELU) {
            v00 = fmaxf(v00, 0.0f); v01 = fmaxf(v01, 0.0f);
            v10 = fmaxf(v10, 0.0f); v11 = fmaxf(v11, 0.0f);
        }
        A_s[r0 * LDA + c0]           = to_tf32(v00);
        A_s[r0 * LDA + c0 + 1]       = to_tf32(v01);
        A_s[(r0 + 8) * LDA + c0]     = to_tf32(v10);
        A_s[(r0 + 8) * LDA + c0 + 1] = to_tf32(v11);
    }
}

// Edge pipeline: gather [x[row] | x[col] | edge_attr] -> tf32 MMA MLP(288->256->256->128)
// -> scatter-add into g_aggr[col].
__global__ __launch_bounds__(NTE, 1) void edge_kernel(
    const float* __restrict__ x, const int* __restrict__ ei,
    const float* __restrict__ ea,
    const float* __restrict__ b1, const float* __restrict__ b2,
    const float* __restrict__ b3,
    int E)
{
    extern __shared__ float smem[];
    float*  A_s  = smem;                            // [TE][LDA]
    float4* w_s4 = (float4*)(A_s + TE * LDA);       // 2 x WBUF float4 (64KB)
    int*    idx_s = (int*)(w_s4 + 2 * WBUF);        // row[TE], col[TE]
    int* row_s = idx_s;
    int* col_s = idx_s + TE;

    const int tid = threadIdx.x;
    const int l = tid & 31, wid = tid >> 5;
    const int wm = wid & 7, wn = wid >> 3;
    const int e0 = blockIdx.x * TE;

    // Load edge endpoint indices (int32, layout [2][E])
    if (tid < 2 * TE) {
        int k = tid & (TE - 1);
        int which = tid >> 7;                 // 0: row, 1: col
        int e = e0 + k;
        int v = 0;
        if (e < E) v = ei[(size_t)which * E + e];
        idx_s[tid] = v;
    }
    __syncthreads();

    // Gather features (tf32-rounded): per edge 72 float4 = x[row] | x[col] | ea
    for (int t = tid; t < TE * 72; t += NTE) {
        int e = t / 72, j = t % 72;
        float4 v;
        int dstoff;
        if (e0 + e < E) {
            if (j < 32)      { v = ((const float4*)(x + (size_t)row_s[e] * ND))[j];        dstoff = j * 4; }
            else if (j < 64) { v = ((const float4*)(x + (size_t)col_s[e] * ND))[j - 32];   dstoff = 128 + (j - 32) * 4; }
            else             { v = ((const float4*)(ea + (size_t)(e0 + e) * ED))[j - 64];  dstoff = 256 + (j - 64) * 4; }
        } else {
            v = make_float4(0.f, 0.f, 0.f, 0.f);
            dstoff = (j < 32) ? j * 4 : (j < 64) ? 128 + (j - 32) * 4 : 256 + (j - 64) * 4;
        }
        float* d = A_s + e * LDA + dstoff;
        d[0] = to_tf32(v.x); d[1] = to_tf32(v.y); d[2] = to_tf32(v.z); d[3] = to_tf32(v.w);
    }
    // (first __syncthreads inside do_gemm_frag protects A_s)

    float acc[16][4];

    // GEMM1: [128,288] x [288,256] -> relu -> A_s
    do_gemm_frag<IN1, HD>(A_s, g_W1f, w_s4, acc, tid);
    epi_store<16, true>(acc, b1, A_s, tid);

    // GEMM2: [128,256] x [256,256] -> relu -> A_s
    do_gemm_frag<HD, HD>(A_s, g_W2f, w_s4, acc, tid);
    epi_store<16, true>(acc, b2, A_s, tid);

    // GEMM3: [128,256] x [256,128] -> +b3 -> scatter-add to g_aggr[col]
    do_gemm_frag<HD, ND>(A_s, g_W3f, w_s4, acc, tid);
    {
        const int r0 = wm * 16 + (l >> 2);
        const int r1 = r0 + 8;
        const bool ok0 = (e0 + r0) < E, ok1 = (e0 + r1) < E;
        float* dst0 = g_aggr + (size_t)col_s[r0] * ND;
        float* dst1 = g_aggr + (size_t)col_s[r1] * ND;
        #pragma unroll
        for (int nt = 0; nt < 8; nt++) {
            int c0 = (wn * 8 + nt) * 8 + (l & 3) * 2;
            float bb0 = b3[c0], bb1 = b3[c0 + 1];
            if (ok0) {
                atomicAdd(dst0 + c0,     acc[nt][0] + bb0);
                atomicAdd(dst0 + c0 + 1, acc[nt][1] + bb1);
            }
            if (ok1) {
                atomicAdd(dst1 + c0,     acc[nt][2] + bb0);
                atomicAdd(dst1 + c0 + 1, acc[nt][3] + bb1);
            }
        }
    }
}

// ---------------- Node pipeline (SIMT fp32) ----------------
#define BK 16
#define NTN 256
#define TN 64

template<int K, int NCOL, int JT>
__device__ __forceinline__ void gemm_tile(
    const float* __restrict__ A_s, int lda,
    const float* __restrict__ W, const float* __restrict__ bias,
    float* w_s, float (&acc)[8][JT], int tid)
{
    const int tx = tid & 31, ty = tid >> 5;
    #pragma unroll
    for (int j = 0; j < JT; j++) {
        float bj = bias[tx + j * 32];
        #pragma unroll
        for (int i = 0; i < 8; i++) acc[i][j] = bj;
    }
    #pragma unroll 1
    for (int k0 = 0; k0 < K; k0 += BK) {
        __syncthreads();
        #pragma unroll
        for (int lld = 0; lld < (BK * NCOL) / NTN; lld++) {
            int idx = lld * NTN + tid;
            w_s[idx] = W[(k0 + idx / NCOL) * NCOL + (idx % NCOL)];
        }
        __syncthreads();
        #pragma unroll
        for (int kk = 0; kk < BK; kk++) {
            float a[8], b[JT];
            #pragma unroll
            for (int i = 0; i < 8; i++) a[i] = A_s[(ty * 8 + i) * lda + k0 + kk];
            #pragma unroll
            for (int j = 0; j < JT; j++) b[j] = w_s[kk * NCOL + tx + j * 32];
            #pragma unroll
            for (int i = 0; i < 8; i++)
                #pragma unroll
                for (int j = 0; j < JT; j++)
                    acc[i][j] = fmaf(a[i], b[j], acc[i][j]);
        }
    }
    __syncthreads();
}

__global__ __launch_bounds__(NTN) void node_kernel(
    const float* __restrict__ x,
    const float* __restrict__ Wn1, const float* __restrict__ bn1,
    const float* __restrict__ Wn2, const float* __restrict__ bn2,
    const float* __restrict__ gamma, const float* __restrict__ beta,
    float* __restrict__ out, int Nn)
{
    extern __shared__ float smem[];
    float* in_s = smem;             // [TN][HD] : cols 0..127 = x, 128..255 = aggr
    float* h_s  = in_s + TN * HD;   // [TN][HD]
    float* w_s  = h_s + TN * HD;    // [BK][HD]

    const int tid = threadIdx.x;
    const int tx = tid & 31, ty = tid >> 5;
    const int n0 = blockIdx.x * TN;

    for (int t = tid; t < TN * 64; t += NTN) {
        int r = t >> 6, j = t & 63;
        int n = n0 + r; if (n >= Nn) n = Nn - 1;   // clamp (stores are guarded)
        float4 v = (j < 32) ? ((const float4*)(x + (size_t)n * ND))[j]
                            : ((const float4*)(g_aggr + (size_t)n * ND))[j - 32];
        float* d = in_s + r * HD + j * 4;
        d[0] = v.x; d[1] = v.y; d[2] = v.z; d[3] = v.w;
    }

    float acc[8][8];
    gemm_tile<HD, HD, 8>(in_s, HD, Wn1, bn1, w_s, acc, tid);
    #pragma unroll
    for (int i = 0; i < 8; i++)
        #pragma unroll
        for (int j = 0; j < 8; j++)
            h_s[(ty * 8 + i) * HD + tx + j * 32] = fmaxf(acc[i][j], 0.0f);

    float acc2[8][4];
    gemm_tile<HD, ND, 4>(h_s, HD, Wn2, bn2, w_s, acc2, tid);

    #pragma unroll
    for (int i = 0; i < 8; i++) {
        int r = ty * 8 + i;
        #pragma unroll
        for (int j = 0; j < 4; j++) {
            int c = tx + j * 32;
            in_s[r * HD + c] += acc2[i][j];
        }
    }
    __syncthreads();

    #pragma unroll 1
    for (int rr = 0; rr < 8; rr++) {
        int r = ty * 8 + rr;
        float4 v = *(const float4*)(in_s + r * HD + tx * 4);
        float s  = v.x + v.y + v.z + v.w;
        float sq = v.x * v.x + v.y * v.y + v.z * v.z + v.w * v.w;
        #pragma unroll
        for (int o = 16; o > 0; o >>= 1) {
            s  += __shfl_xor_sync(0xffffffffu, s, o);
            sq += __shfl_xor_sync(0xffffffffu, sq, o);
        }
        float mean = s * (1.0f / ND);
        float var  = sq * (1.0f / ND) - mean * mean;
        float rstd = rsqrtf(var + 1e-5f);
        int n = n0 + r;
        if (n < Nn) {
            float4 g  = ((const float4*)gamma)[tx];
            float4 bb = ((const float4*)beta)[tx];
            float4 o4;
            o4.x = (v.x - mean) * rstd * g.x + bb.x;
            o4.y = (v.y - mean) * rstd * g.y + bb.y;
            o4.z = (v.z - mean) * rstd * g.z + bb.z;
            o4.w = (v.w - mean) * rstd * g.w + bb.w;
            ((float4*)(out + (size_t)n * ND))[tx] = o4;
        }
    }
}

extern "C" void kernel_launch(void* const* d_in, const int* in_sizes, int n_in,
                              void* d_out, int out_size) {
    const float* x   = (const float*)d_in[0];
    const int*   ei  = (const int*)d_in[1];
    const float* ea  = (const float*)d_in[2];
    const float* W1  = (const float*)d_in[3];
    const float* b1  = (const float*)d_in[4];
    const float* W2  = (const float*)d_in[5];
    const float* b2  = (const float*)d_in[6];
    const float* W3  = (const float*)d_in[7];
    const float* b3  = (const float*)d_in[8];
    const float* Wn1 = (const float*)d_in[9];
    const float* bn1 = (const float*)d_in[10];
    const float* Wn2 = (const float*)d_in[11];
    const float* bn2 = (const float*)d_in[12];
    const float* gm  = (const float*)d_in[13];
    const float* bt  = (const float*)d_in[14];
    float* out = (float*)d_out;

    const int N = in_sizes[0] / ND;
    const int E = in_sizes[1] / 2;

    const int EDGE_SMEM = TE * LDA * 4 + 2 * WBUF * 16 + 2 * TE * 4;   // ~211 KB
    const int NODE_SMEM = (TN * HD * 2 + BK * HD) * 4;
    cudaFuncSetAttribute(edge_kernel, cudaFuncAttributeMaxDynamicSharedMemorySize, EDGE_SMEM);
    cudaFuncSetAttribute(node_kernel, cudaFuncAttributeMaxDynamicSharedMemorySize, NODE_SMEM);

    int zero_blocks = (N * ND + 255) / 256;
    if (zero_blocks > 4096) zero_blocks = 4096;
    zero_kernel<<<zero_blocks, 256>>>(N * ND);

    // Pre-permute weights into fragment order. Destination arrays are resolved
    // in device code (which-selector) — never pass a __device__ symbol's host
    // shadow address to a kernel.
    perm_kernel<<<(IN1 * HD / 2 + 255) / 256, 256>>>(W1, IN1, HD, 0);
    perm_kernel<<<(HD * HD / 2 + 255) / 256, 256>>>(W2, HD, HD, 1);
    perm_kernel<<<(HD * ND / 2 + 255) / 256, 256>>>(W3, HD, ND, 2);

    edge_kernel<<<(E + TE - 1) / TE, NTE, EDGE_SMEM>>>(
        x, ei, ea, b1, b2, b3, E);

    node_kernel<<<(N + TN - 1) / TN, NTN, NODE_SMEM>>>(
        x, Wn1, bn1, Wn2, bn2, gm, bt, out, N);
}

// round 9
// speedup vs baseline: 4.3083x; 1.2468x over previous
#include <cuda_runtime.h>
#include <cstdint>

#define ND 128
#define ED 32
#define HD 256
#define TE 128           // edges per block (M tile)
#define NTE 512          // 16 warps: 4 in M (32 rows each) x 4 in N
#define LDA 292          // A row stride (floats): 292*4 % 128 == 16 -> conflict-free LDSM
#define LDAP 132         // pre-kernel A stride: 132*4 % 128 == 16
#define WBUF 2048        // B double-buffer stride in float4 (32KB slab)

// Scratch (device-resolved symbols only; host shadow address trap!)
__device__ float g_aggr[(size_t)50176 * ND];
__device__ float g_P[(size_t)50176 * HD];     // x @ W1[0:128]
__device__ float g_Q[(size_t)50176 * HD];     // x @ W1[128:256]
__device__ float4 g_W1cf[ED * HD / 4];        // 2048  (W1 rows 256..287)
__device__ float4 g_W2f[HD * HD / 4];         // 16384
__device__ float4 g_W3f[HD * ND / 4];         // 8192
__device__ float4 g_W1af[ND * HD / 4];        // 8192
__device__ float4 g_W1bf[ND * HD / 4];        // 8192

__global__ void zero_kernel(int n) {
    int i = blockIdx.x * blockDim.x + threadIdx.x;
    int stride = gridDim.x * blockDim.x;
    for (; i < n; i += stride) g_aggr[i] = 0.0f;
}

__device__ __forceinline__ float to_tf32(float x) {
    uint32_t r; asm("cvt.rna.tf32.f32 %0, %1;" : "=r"(r) : "f"(x));
    return __uint_as_float(r);
}

// Permute W [K][N] row-major into MMA B-fragment slab order (same layout as the
// validated passing kernel). Destination resolved in DEVICE code.
__global__ void perm_kernel(const float* __restrict__ W, int K, int N, int which) {
    float2* Wf = (which == 0) ? (float2*)g_W1cf
               : (which == 1) ? (float2*)g_W2f
               : (which == 2) ? (float2*)g_W3f
               : (which == 3) ? (float2*)g_W1af
                              : (float2*)g_W1bf;
    int i = blockIdx.x * blockDim.x + threadIdx.x;
    int total = K * N / 2;
    if (i >= total) return;
    int l = i & 31;
    int t = i >> 5;
    int nt = t % (N >> 3);
    int q = t / (N >> 3);
    int kk = q & 3, s = q >> 2;
    int k = s * 32 + kk * 8 + (l & 3);
    int n = nt * 8 + (l >> 2);
    float2 v;
    v.x = to_tf32(W[(size_t)k * N + n]);
    v.y = to_tf32(W[(size_t)(k + 4) * N + n]);
    Wf[i] = v;
}

__device__ __forceinline__ void mma_tf32(float (&c)[4], uint32_t a0, uint32_t a1,
                                         uint32_t a2, uint32_t a3, uint32_t b0, uint32_t b1) {
    asm volatile("mma.sync.aligned.m16n8k8.row.col.f32.tf32.tf32.f32 "
        "{%0,%1,%2,%3}, {%4,%5,%6,%7}, {%8,%9}, {%0,%1,%2,%3};"
        : "+f"(c[0]), "+f"(c[1]), "+f"(c[2]), "+f"(c[3])
        : "r"(a0), "r"(a1), "r"(a2), "r"(a3), "r"(b0), "r"(b1));
}

__device__ __forceinline__ void ldsm4(uint32_t &a0, uint32_t &a1, uint32_t &a2, uint32_t &a3,
                                      const float* p) {
    uint32_t addr = (uint32_t)__cvta_generic_to_shared(p);
    asm volatile("ldmatrix.sync.aligned.m8n8.x4.shared.b16 {%0,%1,%2,%3}, [%4];"
        : "=r"(a0), "=r"(a1), "=r"(a2), "=r"(a3) : "r"(addr));
}

__device__ __forceinline__ void cp_async16(void* smem_dst, const void* gsrc) {
    uint32_t d = (uint32_t)__cvta_generic_to_shared(smem_dst);
    asm volatile("cp.async.cg.shared.global [%0], [%1], 16;" :: "r"(d), "l"(gsrc));
}
__device__ __forceinline__ void cp_commit() { asm volatile("cp.async.commit_group;"); }
__device__ __forceinline__ void cp_wait0()  { asm volatile("cp.async.wait_group 0;" ::: "memory"); }

// Warp-tiled tf32 GEMM, 16 warps: wm=wid&3 (32 rows each), wn=wid>>2 (N/4 cols).
// Each B fragment is loaded once and feeds TWO MMAs (rows mt=0/1) -> half the
// B smem traffic of the previous 16-row tiling. acc[mt][nt][4].
template<int K, int N, int LDA_>
__device__ __forceinline__ void do_gemm2(const float* A_s,
                                         const float4* __restrict__ Wf4,
                                         float4* w_s4, float (&acc)[2][8][4], int tid) {
    const int l = tid & 31, wid = tid >> 5;
    const int wm = wid & 3, wn = wid >> 2;
    constexpr int NT8 = N / 8;          // n-subtiles total
    constexpr int NTW = N / 32;         // n-subtiles per warp (8 for N=256, 4 for N=128)
    constexpr int SLAB4 = NT8 * 64;     // float4 per 32-K slab
    constexpr int S = K / 32;

    #pragma unroll
    for (int mt = 0; mt < 2; mt++)
        #pragma unroll
        for (int nt = 0; nt < NTW; nt++)
            #pragma unroll
            for (int i = 0; i < 4; i++) acc[mt][nt][i] = 0.0f;

    const int a_row0 = wm * 32 + ((l >> 3) & 1) * 8 + (l & 7);
    const int a_col4 = (l >> 4) * 4;

    // prologue: stage slab 0
    #pragma unroll
    for (int t = tid; t < SLAB4; t += NTE) cp_async16(w_s4 + t, Wf4 + t);
    cp_commit();

    #pragma unroll 1
    for (int s = 0; s < S; s++) {
        cp_wait0();
        __syncthreads();          // slab s ready; A_s writes visible on first pass
        if (s + 1 < S) {
            float4* dst = w_s4 + ((s + 1) & 1) * WBUF;
            const float4* src = Wf4 + (size_t)(s + 1) * SLAB4;
            #pragma unroll
            for (int t = tid; t < SLAB4; t += NTE) cp_async16(dst + t, src + t);
            cp_commit();
        }
        const float2* wb = (const float2*)(w_s4 + (s & 1) * WBUF);
        const int k0 = s * 32;
        #pragma unroll
        for (int kk = 0; kk < 4; kk++) {
            uint32_t a[2][4];
            #pragma unroll
            for (int mt = 0; mt < 2; mt++)
                ldsm4(a[mt][0], a[mt][1], a[mt][2], a[mt][3],
                      A_s + (a_row0 + mt * 16) * LDA_ + k0 + kk * 8 + a_col4);
            #pragma unroll
            for (int nt = 0; nt < NTW; nt++) {
                float2 b = wb[(size_t)(kk * NT8 + wn * NTW + nt) * 32 + l];
                uint32_t b0 = __float_as_uint(b.x), b1 = __float_as_uint(b.y);
                mma_tf32(acc[0][nt], a[0][0], a[0][1], a[0][2], a[0][3], b0, b1);
                mma_tf32(acc[1][nt], a[1][0], a[1][1], a[1][2], a[1][3], b0, b1);
            }
        }
    }
    __syncthreads();   // protect A_s / w_s rewrite after this GEMM
}

// Epilogue: acc + bias (+ReLU), tf32-round, store to A_s (N=256 layout).
__device__ __forceinline__ void epi_relu(float (&acc)[2][8][4], const float* __restrict__ bias,
                                         float* A_s, int tid) {
    const int l = tid & 31, wid = tid >> 5;
    const int wm = wid & 3, wn = wid >> 2;
    #pragma unroll
    for (int mt = 0; mt < 2; mt++) {
        int r0 = wm * 32 + mt * 16 + (l >> 2);
        #pragma unroll
        for (int nt = 0; nt < 8; nt++) {
            int c0 = (wn * 8 + nt) * 8 + (l & 3) * 2;
            float bb0 = bias[c0], bb1 = bias[c0 + 1];
            A_s[r0 * LDA + c0]           = to_tf32(fmaxf(acc[mt][nt][0] + bb0, 0.f));
            A_s[r0 * LDA + c0 + 1]       = to_tf32(fmaxf(acc[mt][nt][1] + bb1, 0.f));
            A_s[(r0 + 8) * LDA + c0]     = to_tf32(fmaxf(acc[mt][nt][2] + bb0, 0.f));
            A_s[(r0 + 8) * LDA + c0 + 1] = to_tf32(fmaxf(acc[mt][nt][3] + bb1, 0.f));
        }
    }
}

// Edge pipeline: h1 = relu(ea@W1c + P[row] + Q[col] + b1) -> GEMM2 -> GEMM3 -> scatter.
__global__ __launch_bounds__(NTE, 1) void edge_kernel(
    const float* __restrict__ x, const int* __restrict__ ei,
    const float* __restrict__ ea,
    const float* __restrict__ b1, const float* __restrict__ b2,
    const float* __restrict__ b3,
    int E)
{
    extern __shared__ float smem[];
    float*  A_s  = smem;                            // [TE][LDA]
    float4* w_s4 = (float4*)(A_s + TE * LDA);       // 2 x WBUF float4
    int*    idx_s = (int*)(w_s4 + 2 * WBUF);        // row[TE], col[TE]
    int* row_s = idx_s;
    int* col_s = idx_s + TE;

    const int tid = threadIdx.x;
    const int l = tid & 31, wid = tid >> 5;
    const int wm = wid & 3, wn = wid >> 2;
    const int e0 = blockIdx.x * TE;

    if (tid < 2 * TE) {
        int k = tid & (TE - 1);
        int which = tid >> 7;
        int e = e0 + k;
        idx_s[tid] = (e < E) ? ei[(size_t)which * E + e] : 0;
    }
    __syncthreads();

    // gather ea only (K=32): per edge 8 float4, tf32-rounded
    for (int t = tid; t < TE * 8; t += NTE) {
        int e = t >> 3, j = t & 7;
        float4 v = (e0 + e < E) ? ((const float4*)(ea + (size_t)(e0 + e) * ED))[j]
                                : make_float4(0.f, 0.f, 0.f, 0.f);
        float* d = A_s + e * LDA + j * 4;
        d[0] = to_tf32(v.x); d[1] = to_tf32(v.y); d[2] = to_tf32(v.z); d[3] = to_tf32(v.w);
    }

    float acc[2][8][4];

    // GEMM1c: [128,32] x W1c[32,256]; epilogue adds P[row] + Q[col] + b1, relu.
    do_gemm2<ED, HD, LDA>(A_s, g_W1cf, w_s4, acc, tid);
    #pragma unroll
    for (int mt = 0; mt < 2; mt++) {
        int r0 = wm * 32 + mt * 16 + (l >> 2);
        int r1 = r0 + 8;
        const float* P0 = g_P + (size_t)row_s[r0] * HD;
        const float* Q0 = g_Q + (size_t)col_s[r0] * HD;
        const float* P1 = g_P + (size_t)row_s[r1] * HD;
        const float* Q1 = g_Q + (size_t)col_s[r1] * HD;
        #pragma unroll
        for (int nt = 0; nt < 8; nt++) {
            int c0 = (wn * 8 + nt) * 8 + (l & 3) * 2;
            float2 p0 = *(const float2*)(P0 + c0);
            float2 q0 = *(const float2*)(Q0 + c0);
            float2 p1 = *(const float2*)(P1 + c0);
            float2 q1 = *(const float2*)(Q1 + c0);
            float bb0 = b1[c0], bb1 = b1[c0 + 1];
            A_s[r0 * LDA + c0]     = to_tf32(fmaxf(acc[mt][nt][0] + p0.x + q0.x + bb0, 0.f));
            A_s[r0 * LDA + c0 + 1] = to_tf32(fmaxf(acc[mt][nt][1] + p0.y + q0.y + bb1, 0.f));
            A_s[r1 * LDA + c0]     = to_tf32(fmaxf(acc[mt][nt][2] + p1.x + q1.x + bb0, 0.f));
            A_s[r1 * LDA + c0 + 1] = to_tf32(fmaxf(acc[mt][nt][3] + p1.y + q1.y + bb1, 0.f));
        }
    }

    // GEMM2: [128,256] x W2 -> relu -> A_s
    do_gemm2<HD, HD, LDA>(A_s, g_W2f, w_s4, acc, tid);
    epi_relu(acc, b2, A_s, tid);

    // GEMM3: [128,256] x W3[256,128] -> +b3 -> scatter-add to g_aggr[col]
    do_gemm2<HD, ND, LDA>(A_s, g_W3f, w_s4, acc, tid);
    #pragma unroll
    for (int mt = 0; mt < 2; mt++) {
        int r0 = wm * 32 + mt * 16 + (l >> 2);
        int r1 = r0 + 8;
        bool ok0 = (e0 + r0) < E, ok1 = (e0 + r1) < E;
        float* dst0 = g_aggr + (size_t)col_s[r0] * ND;
        float* dst1 = g_aggr + (size_t)col_s[r1] * ND;
        #pragma unroll
        for (int nt = 0; nt < 4; nt++) {
            int c0 = (wn * 4 + nt) * 8 + (l & 3) * 2;
            float bb0 = b3[c0], bb1 = b3[c0 + 1];
            if (ok0) {
                atomicAdd(dst0 + c0,     acc[mt][nt][0] + bb0);
                atomicAdd(dst0 + c0 + 1, acc[mt][nt][1] + bb1);
            }
            if (ok1) {
                atomicAdd(dst1 + c0,     acc[mt][nt][2] + bb0);
                atomicAdd(dst1 + c0 + 1, acc[mt][nt][3] + bb1);
            }
        }
    }
}

// Precompute P = x@W1a, Q = x@W1b per 128-node tile (raw fp32, bias added later).
__global__ __launch_bounds__(NTE, 1) void pre_kernel(const float* __restrict__ x, int Nn)
{
    extern __shared__ float smem[];
    float*  A_s  = smem;                            // [128][LDAP]
    float4* w_s4 = (float4*)(A_s + TE * LDAP);

    const int tid = threadIdx.x;
    const int l = tid & 31, wid = tid >> 5;
    const int wm = wid & 3, wn = wid >> 2;
    const int n0 = blockIdx.x * TE;

    for (int t = tid; t < TE * 32; t += NTE) {
        int r = t >> 5, j = t & 31;
        int n = n0 + r; if (n >= Nn) n = Nn - 1;     // clamp; stores guarded
        float4 v = ((const float4*)(x + (size_t)n * ND))[j];
        float* d = A_s + r * LDAP + j * 4;
        d[0] = to_tf32(v.x); d[1] = to_tf32(v.y); d[2] = to_tf32(v.z); d[3] = to_tf32(v.w);
    }

    float acc[2][8][4];
    #pragma unroll 1
    for (int which = 0; which < 2; which++) {
        do_gemm2<ND, HD, LDAP>(A_s, which ? g_W1bf : g_W1af, w_s4, acc, tid);
        float* O = which ? g_Q : g_P;
        #pragma unroll
        for (int mt = 0; mt < 2; mt++) {
            int r0 = wm * 32 + mt * 16 + (l >> 2);
            int nr0 = n0 + r0, nr1 = n0 + r0 + 8;
            #pragma unroll
            for (int nt = 0; nt < 8; nt++) {
                int c0 = (wn * 8 + nt) * 8 + (l & 3) * 2;
                if (nr0 < Nn) *(float2*)(O + (size_t)nr0 * HD + c0) =
                    make_float2(acc[mt][nt][0], acc[mt][nt][1]);
                if (nr1 < Nn) *(float2*)(O + (size_t)nr1 * HD + c0) =
                    make_float2(acc[mt][nt][2], acc[mt][nt][3]);
            }
        }
    }
}

// ---------------- Node pipeline (SIMT fp32, unchanged) ----------------
#define BK 16
#define NTN 256
#define TN 64

template<int K, int NCOL, int JT>
__device__ __forceinline__ void gemm_tile(
    const float* __restrict__ A_s, int lda,
    const float* __restrict__ W, const float* __restrict__ bias,
    float* w_s, float (&acc)[8][JT], int tid)
{
    const int tx = tid & 31, ty = tid >> 5;
    #pragma unroll
    for (int j = 0; j < JT; j++) {
        float bj = bias[tx + j * 32];
        #pragma unroll
        for (int i = 0; i < 8; i++) acc[i][j] = bj;
    }
    #pragma unroll 1
    for (int k0 = 0; k0 < K; k0 += BK) {
        __syncthreads();
        #pragma unroll
        for (int lld = 0; lld < (BK * NCOL) / NTN; lld++) {
            int idx = lld * NTN + tid;
            w_s[idx] = W[(k0 + idx / NCOL) * NCOL + (idx % NCOL)];
        }
        __syncthreads();
        #pragma unroll
        for (int kk = 0; kk < BK; kk++) {
            float a[8], b[JT];
            #pragma unroll
            for (int i = 0; i < 8; i++) a[i] = A_s[(ty * 8 + i) * lda + k0 + kk];
            #pragma unroll
            for (int j = 0; j < JT; j++) b[j] = w_s[kk * NCOL + tx + j * 32];
            #pragma unroll
            for (int i = 0; i < 8; i++)
                #pragma unroll
                for (int j = 0; j < JT; j++)
                    acc[i][j] = fmaf(a[i], b[j], acc[i][j]);
        }
    }
    __syncthreads();
}

__global__ __launch_bounds__(NTN) void node_kernel(
    const float* __restrict__ x,
    const float* __restrict__ Wn1, const float* __restrict__ bn1,
    const float* __restrict__ Wn2, const float* __restrict__ bn2,
    const float* __restrict__ gamma, const float* __restrict__ beta,
    float* __restrict__ out, int Nn)
{
    extern __shared__ float smem[];
    float* in_s = smem;
    float* h_s  = in_s + TN * HD;
    float* w_s  = h_s + TN * HD;

    const int tid = threadIdx.x;
    const int tx = tid & 31, ty = tid >> 5;
    const int n0 = blockIdx.x * TN;

    for (int t = tid; t < TN * 64; t += NTN) {
        int r = t >> 6, j = t & 63;
        int n = n0 + r; if (n >= Nn) n = Nn - 1;
        float4 v = (j < 32) ? ((const float4*)(x + (size_t)n * ND))[j]
                            : ((const float4*)(g_aggr + (size_t)n * ND))[j - 32];
        float* d = in_s + r * HD + j * 4;
        d[0] = v.x; d[1] = v.y; d[2] = v.z; d[3] = v.w;
    }

    float acc[8][8];
    gemm_tile<HD, HD, 8>(in_s, HD, Wn1, bn1, w_s, acc, tid);
    #pragma unroll
    for (int i = 0; i < 8; i++)
        #pragma unroll
        for (int j = 0; j < 8; j++)
            h_s[(ty * 8 + i) * HD + tx + j * 32] = fmaxf(acc[i][j], 0.0f);

    float acc2[8][4];
    gemm_tile<HD, ND, 4>(h_s, HD, Wn2, bn2, w_s, acc2, tid);

    #pragma unroll
    for (int i = 0; i < 8; i++) {
        int r = ty * 8 + i;
        #pragma unroll
        for (int j = 0; j < 4; j++)
            in_s[r * HD + tx + j * 32] += acc2[i][j];
    }
    __syncthreads();

    #pragma unroll 1
    for (int rr = 0; rr < 8; rr++) {
        int r = ty * 8 + rr;
        float4 v = *(const float4*)(in_s + r * HD + tx * 4);
        float s  = v.x + v.y + v.z + v.w;
        float sq = v.x * v.x + v.y * v.y + v.z * v.z + v.w * v.w;
        #pragma unroll
        for (int o = 16; o > 0; o >>= 1) {
            s  += __shfl_xor_sync(0xffffffffu, s, o);
            sq += __shfl_xor_sync(0xffffffffu, sq, o);
        }
        float mean = s * (1.0f / ND);
        float var  = sq * (1.0f / ND) - mean * mean;
        float rstd = rsqrtf(var + 1e-5f);
        int n = n0 + r;
        if (n < Nn) {
            float4 g  = ((const float4*)gamma)[tx];
            float4 bb = ((const float4*)beta)[tx];
            float4 o4;
            o4.x = (v.x - mean) * rstd * g.x + bb.x;
            o4.y = (v.y - mean) * rstd * g.y + bb.y;
            o4.z = (v.z - mean) * rstd * g.z + bb.z;
            o4.w = (v.w - mean) * rstd * g.w + bb.w;
            ((float4*)(out + (size_t)n * ND))[tx] = o4;
        }
    }
}

extern "C" void kernel_launch(void* const* d_in, const int* in_sizes, int n_in,
                              void* d_out, int out_size) {
    const float* x   = (const float*)d_in[0];
    const int*   ei  = (const int*)d_in[1];
    const float* ea  = (const float*)d_in[2];
    const float* W1  = (const float*)d_in[3];
    const float* b1  = (const float*)d_in[4];
    const float* W2  = (const float*)d_in[5];
    const float* b2  = (const float*)d_in[6];
    const float* W3  = (const float*)d_in[7];
    const float* b3  = (const float*)d_in[8];
    const float* Wn1 = (const float*)d_in[9];
    const float* bn1 = (const float*)d_in[10];
    const float* Wn2 = (const float*)d_in[11];
    const float* bn2 = (const float*)d_in[12];
    const float* gm  = (const float*)d_in[13];
    const float* bt  = (const float*)d_in[14];
    float* out = (float*)d_out;

    const int N = in_sizes[0] / ND;
    const int E = in_sizes[1] / 2;

    const int EDGE_SMEM = TE * LDA * 4 + 2 * WBUF * 16 + 2 * TE * 4;   // ~216 KB
    const int PRE_SMEM  = TE * LDAP * 4 + 2 * WBUF * 16;               // ~133 KB
    const int NODE_SMEM = (TN * HD * 2 + BK * HD) * 4;
    cudaFuncSetAttribute(edge_kernel, cudaFuncAttributeMaxDynamicSharedMemorySize, EDGE_SMEM);
    cudaFuncSetAttribute(pre_kernel,  cudaFuncAttributeMaxDynamicSharedMemorySize, PRE_SMEM);
    cudaFuncSetAttribute(node_kernel, cudaFuncAttributeMaxDynamicSharedMemorySize, NODE_SMEM);

    int zero_blocks = (N * ND + 255) / 256;
    if (zero_blocks > 4096) zero_blocks = 4096;
    zero_kernel<<<zero_blocks, 256>>>(N * ND);

    // Weight permutes (destinations resolved in device code)
    perm_kernel<<<(ED * HD / 2 + 255) / 256, 256>>>(W1 + (size_t)2 * ND * HD, ED, HD, 0);
    perm_kernel<<<(HD * HD / 2 + 255) / 256, 256>>>(W2, HD, HD, 1);
    perm_kernel<<<(HD * ND / 2 + 255) / 256, 256>>>(W3, HD, ND, 2);
    perm_kernel<<<(ND * HD / 2 + 255) / 256, 256>>>(W1, ND, HD, 3);
    perm_kernel<<<(ND * HD / 2 + 255) / 256, 256>>>(W1 + (size_t)ND * HD, ND, HD, 4);

    pre_kernel<<<(N + TE - 1) / TE, NTE, PRE_SMEM>>>(x, N);

    edge_kernel<<<(E + TE - 1) / TE, NTE, EDGE_SMEM>>>(x, ei, ea, b1, b2, b3, E);

    node_kernel<<<(N + TN - 1) / TN, NTN, NODE_SMEM>>>(
        x, Wn1, bn1, Wn2, bn2, gm, bt, out, N);
}